// round 5
// baseline (speedup 1.0000x reference)
#include <cuda_runtime.h>
#include <cuda_bf16.h>
#include <math.h>

// ---------------------------------------------------------------------------
// LSTM: S=512, B=64, I=256, H=512
// out = [h_seq (S,B,H) | h_final (B,H) | c_final (B,H)]  (fp32)
// ---------------------------------------------------------------------------

#define S_LEN 512
#define BATCH 64
#define IN_DIM 256
#define HID 512
#define G4 2048              // 4*H
#define BH (BATCH*HID)       // 32768
#define BG (BATCH*G4)        // 131072
#define HPAD 516             // padded row stride (floats)
#define NCTA 128

// -------------------- device scratch (static: no allocs allowed) ------------
__device__ float g_xp[(size_t)S_LEN * BATCH * G4];   // x@Wx + bx + bh
__device__ float g_Wx[IN_DIM * G4];                  // packed (K x 4H)
__device__ float g_WhT[(size_t)G4 * HID];            // WhT[col][k]
__device__ float g_bias[G4];                         // bx + bh
__device__ unsigned int g_barc[4 * 32];              // per-bg counters, 128B apart

// -------------------- f32x2 helpers (Blackwell packed fp32) -----------------
__device__ __forceinline__ void fma2(unsigned long long& d,
                                     unsigned long long a,
                                     unsigned long long b) {
    asm("fma.rn.f32x2 %0, %1, %2, %0;" : "+l"(d) : "l"(a), "l"(b));
}
__device__ __forceinline__ unsigned long long dup2(float a) {
    unsigned long long d;
    asm("mov.b64 %0, {%1, %1};" : "=l"(d) : "f"(a));
    return d;
}
__device__ __forceinline__ float sum2(unsigned long long v) {
    float lo, hi;
    asm("mov.b64 {%0, %1}, %2;" : "=f"(lo), "=f"(hi) : "l"(v));
    return lo + hi;
}

// fast activations: ex2.approx + rcp.approx (rel err ~1e-6, safe vs 1e-3 tol)
__device__ __forceinline__ float fast_exp(float x) {
    float e;
    asm("ex2.approx.f32 %0, %1;" : "=f"(e) : "f"(x * 1.4426950408889634f));
    return e;
}
__device__ __forceinline__ float fast_rcp(float x) {
    float r;
    asm("rcp.approx.f32 %0, %1;" : "=f"(r) : "f"(x));
    return r;
}
__device__ __forceinline__ float fast_sigmoid(float x) {
    return fast_rcp(1.f + fast_exp(-x));
}
__device__ __forceinline__ float fast_tanh(float x) {
    return 2.f * fast_rcp(1.f + fast_exp(-2.f * x)) - 1.f;
}

__device__ __forceinline__ void cpasync16(unsigned dst, const void* src) {
    asm volatile("cp.async.cg.shared.global [%0], [%1], 16;"
                 :: "r"(dst), "l"(src));
}

// -------------------- init / pack kernels -----------------------------------
__global__ void bar_init_kernel() {
    int i = threadIdx.x;
    if (i < 4 * 32) g_barc[i] = 0u;
}

__global__ void pack_wx_kernel(
    const float* __restrict__ Wf, const float* __restrict__ Wi,
    const float* __restrict__ Wo, const float* __restrict__ Wg,
    const float* __restrict__ bxf, const float* __restrict__ bhf,
    const float* __restrict__ bxi, const float* __restrict__ bhi,
    const float* __restrict__ bxo, const float* __restrict__ bho,
    const float* __restrict__ bxg, const float* __restrict__ bhg)
{
    int idx = blockIdx.x * blockDim.x + threadIdx.x;
    if (idx < IN_DIM * G4) {
        int k = idx >> 11;
        int col = idx & 2047;
        int g = col >> 9;
        int jj = col & 511;
        const float* W = (g == 0) ? Wf : (g == 1) ? Wi : (g == 2) ? Wo : Wg;
        g_Wx[idx] = W[k * HID + jj];
    }
    if (idx < G4) {
        int g = idx >> 9, jj = idx & 511;
        const float* bx = (g == 0) ? bxf : (g == 1) ? bxi : (g == 2) ? bxo : bxg;
        const float* bh = (g == 0) ? bhf : (g == 1) ? bhi : (g == 2) ? bho : bhg;
        g_bias[idx] = bx[jj] + bh[jj];
    }
}

__global__ void pack_wh_kernel(
    const float* __restrict__ Wf, const float* __restrict__ Wi,
    const float* __restrict__ Wo, const float* __restrict__ Wg)
{
    int idx = blockIdx.x * blockDim.x + threadIdx.x;
    if (idx < G4 * HID) {
        int col = idx >> 9;
        int k   = idx & 511;
        int g   = col >> 9;
        int jj  = col & 511;
        const float* W = (g == 0) ? Wf : (g == 1) ? Wi : (g == 2) ? Wo : Wg;
        g_WhT[idx] = W[k * HID + jj];   // WhT[col][k] = Wh[k][col]
    }
}

// -------------------- xproj: xp = x @ Wx_cat + bias --------------------------
// M=32768, N=2048, K=256. Tile 128x128, BK=16, 256 threads, TM=8, TN=8 (f32x2).
__global__ __launch_bounds__(256, 2) void xproj_kernel(const float* __restrict__ x)
{
    __shared__ float As[16][132];   // transposed A tile, padded
    __shared__ float Bs[16][128];

    const int tid = threadIdx.x;
    const int tx = tid & 15;        // N direction (x8)
    const int ty = tid >> 4;        // M direction (x8)
    const int bm = blockIdx.y * 128;
    const int bn = blockIdx.x * 128;

    unsigned long long acc[8][4];
#pragma unroll
    for (int i = 0; i < 8; i++) {
#pragma unroll
        for (int jq = 0; jq < 4; jq++) acc[i][jq] = 0ull;
    }

    const int a_m = tid >> 1;            // 0..127
    const int a_k = (tid & 1) << 3;      // 0 or 8
    const int b_r = tid >> 4;            // 0..15
    const int b_c = (tid & 15) << 3;     // 0..120

    const float* Aptr = x + (size_t)bm * IN_DIM;

    for (int kt = 0; kt < IN_DIM; kt += 16) {
        float4 av0 = *(const float4*)(Aptr + (size_t)a_m * IN_DIM + kt + a_k);
        float4 av1 = *(const float4*)(Aptr + (size_t)a_m * IN_DIM + kt + a_k + 4);
        float4 bv0 = *(const float4*)(g_Wx + (size_t)(kt + b_r) * G4 + bn + b_c);
        float4 bv1 = *(const float4*)(g_Wx + (size_t)(kt + b_r) * G4 + bn + b_c + 4);

        As[a_k + 0][a_m] = av0.x; As[a_k + 1][a_m] = av0.y;
        As[a_k + 2][a_m] = av0.z; As[a_k + 3][a_m] = av0.w;
        As[a_k + 4][a_m] = av1.x; As[a_k + 5][a_m] = av1.y;
        As[a_k + 6][a_m] = av1.z; As[a_k + 7][a_m] = av1.w;
        *(float4*)&Bs[b_r][b_c] = bv0;
        *(float4*)&Bs[b_r][b_c + 4] = bv1;
        __syncthreads();

#pragma unroll
        for (int kk = 0; kk < 16; kk++) {
            float4 a0 = *(const float4*)&As[kk][ty * 8];
            float4 a1 = *(const float4*)&As[kk][ty * 8 + 4];
            ulonglong2 b0 = *(const ulonglong2*)&Bs[kk][tx * 8];
            ulonglong2 b1 = *(const ulonglong2*)&Bs[kk][tx * 8 + 4];
            float av[8] = {a0.x, a0.y, a0.z, a0.w, a1.x, a1.y, a1.z, a1.w};
#pragma unroll
            for (int i = 0; i < 8; i++) {
                unsigned long long ad = dup2(av[i]);
                fma2(acc[i][0], ad, b0.x);
                fma2(acc[i][1], ad, b0.y);
                fma2(acc[i][2], ad, b1.x);
                fma2(acc[i][3], ad, b1.y);
            }
        }
        __syncthreads();
    }

    const int n0 = bn + tx * 8;
    float4 bias0 = *(const float4*)&g_bias[n0];
    float4 bias1 = *(const float4*)&g_bias[n0 + 4];
#pragma unroll
    for (int i = 0; i < 8; i++) {
        float v[8];
        asm("mov.b64 {%0, %1}, %2;" : "=f"(v[0]), "=f"(v[1]) : "l"(acc[i][0]));
        asm("mov.b64 {%0, %1}, %2;" : "=f"(v[2]), "=f"(v[3]) : "l"(acc[i][1]));
        asm("mov.b64 {%0, %1}, %2;" : "=f"(v[4]), "=f"(v[5]) : "l"(acc[i][2]));
        asm("mov.b64 {%0, %1}, %2;" : "=f"(v[6]), "=f"(v[7]) : "l"(acc[i][3]));
        int m = bm + ty * 8 + i;
        float4 o0 = make_float4(v[0] + bias0.x, v[1] + bias0.y,
                                v[2] + bias0.z, v[3] + bias0.w);
        float4 o1 = make_float4(v[4] + bias1.x, v[5] + bias1.y,
                                v[6] + bias1.z, v[7] + bias1.w);
        *(float4*)&g_xp[(size_t)m * G4 + n0] = o0;
        *(float4*)&g_xp[(size_t)m * G4 + n0 + 4] = o1;
    }
}

// -------------------- recurrence: 2-D persistent, group barriers -------------
// 128 CTAs = 4 batch-groups (bg: 16 batches) x 32 unit-groups (ug: 16 units).
// 512 threads (16 warps, 4/SMSP for latency hiding), 1 CTA/SM.
// Dot thread = 1 gate-row x 2 batches: r=(w&7)*8+(lane&7); db1=(w>>3)*4+(lane>>3),
// db2=db1+8. Per k-iter: 3 LDS.128 + 4 FFMA2 (FMA/crossbar balanced, shallow body).
// Gates regrouped via smem gbuf; activation threads (tid<256) own c in register.
// Barrier: per-bg red.release counter, 32 arrivals, tid0 tight-spin poll.
#define REC_SMEM ((80 * HPAD + 64 * 17) * 4)

__global__ __launch_bounds__(512, 1) void lstm_rec_kernel(float* __restrict__ out)
{
    extern __shared__ float sm[];
    float* h_s  = sm;                  // 16 * HPAD
    float* wh_s = sm + 16 * HPAD;      // 64 * HPAD
    float* gbuf = sm + 80 * HPAD;      // 64 * 17

    const int tid = threadIdx.x;
    const int cta = blockIdx.x;
    const int ug  = cta & 31;          // units [ug*16, ug*16+16)
    const int bg  = cta >> 5;          // batches [bg*16, +16)

    // ---- load Wh slice: wh_s[r][k] = Wh[k][(r>>4)*512 + ug*16 + (r&15)] ----
    for (int idx = tid; idx < 64 * 128; idx += 512) {
        int r  = idx >> 7;
        int k4 = (idx & 127) << 2;
        int col = (r >> 4) * HID + (ug << 4) + (r & 15);
        float4 v = *(const float4*)&g_WhT[(size_t)col * HID + k4];
        *(float4*)&wh_s[r * HPAD + k4] = v;
    }
    __syncthreads();

    // ---- dot-thread mapping ----
    const int w    = tid >> 5;
    const int lane = tid & 31;
    const int r    = (w & 7) * 8 + (lane & 7);        // gate-row [0,64)
    const int db1  = (w >> 3) * 4 + (lane >> 3);      // local batch [0,8)
    const int db2  = db1 + 8;                         // [8,16)

    const ulonglong2* hp1 = (const ulonglong2*)(h_s + db1 * HPAD);
    const ulonglong2* hp2 = (const ulonglong2*)(h_s + db2 * HPAD);
    const ulonglong2* wp  = (const ulonglong2*)(wh_s + r * HPAD);

    // ---- activation-thread mapping (tid < 256): (b,u) ----
    const int ab = tid >> 4;                 // local batch 0..15 (for tid<256)
    const int au = tid & 15;                 // local unit 0..15
    const int gb = bg * 16 + ab;             // global batch
    const int gj = (ug << 4) + au;           // global hidden unit
    const bool is_act = (tid < 256);

    const unsigned hbase = (unsigned)__cvta_generic_to_shared(h_s);
    unsigned int* barp = &g_barc[bg * 32];

    const size_t xof = (size_t)gb * G4 + gj;
    float c0 = 0.f, c1 = 0.f, c2 = 0.f, c3 = 0.f;
    if (is_act) {
        c0 = g_xp[xof];
        c1 = g_xp[xof + 512];
        c2 = g_xp[xof + 1024];
        c3 = g_xp[xof + 1536];
    }

    float cval = 0.f;

    for (int t = 0; t < S_LEN; t++) {
        if (t > 0) {
            // stage h(t-1)[bg batches] : 16 rows x 512 floats = 32KB
            const float4* src = (const float4*)(out + (size_t)(t - 1) * BH
                                                + (size_t)(bg * 16) * HID);
#pragma unroll
            for (int i = 0; i < 4; i++) {            // 2048 float4 / 512 thr
                int idx = tid + (i << 9);
                int row = idx >> 7;
                int col = (idx & 127) << 2;
                cpasync16(hbase + (unsigned)(row * HPAD + col) * 4u,
                          (const void*)(src + idx));
            }
            asm volatile("cp.async.commit_group;");
            asm volatile("cp.async.wait_group 0;" ::: "memory");
            __syncthreads();
        }

        // prefetch xp for t+1 (hidden under dot loop)
        float n0 = 0.f, n1 = 0.f, n2 = 0.f, n3 = 0.f;
        if (is_act && (t + 1 < S_LEN)) {
            size_t nb = (size_t)(t + 1) * BG + xof;
            n0 = g_xp[nb]; n1 = g_xp[nb + 512];
            n2 = g_xp[nb + 1024]; n3 = g_xp[nb + 1536];
        }

        if (t > 0) {
            unsigned long long a1x = 0ull, a1y = 0ull, a2x = 0ull, a2y = 0ull;
#pragma unroll 8
            for (int k = 0; k < 128; k++) {
                ulonglong2 wv = wp[k];
                ulonglong2 h1 = hp1[k];
                ulonglong2 h2 = hp2[k];
                fma2(a1x, h1.x, wv.x); fma2(a1y, h1.y, wv.y);
                fma2(a2x, h2.x, wv.x); fma2(a2y, h2.y, wv.y);
            }
            gbuf[r * 17 + db1] = sum2(a1x) + sum2(a1y);
            gbuf[r * 17 + db2] = sum2(a2x) + sum2(a2y);
            __syncthreads();
        }

        // ---- activation: thread (ab, au), tid<256 ----
        float hval = 0.f;
        if (is_act) {
            float gf = c0, gi = c1, go = c2, gg = c3;
            if (t > 0) {
                gf += gbuf[(au +  0) * 17 + ab];
                gi += gbuf[(au + 16) * 17 + ab];
                go += gbuf[(au + 32) * 17 + ab];
                gg += gbuf[(au + 48) * 17 + ab];
            }
            c0 = n0; c1 = n1; c2 = n2; c3 = n3;

            float fg = fast_sigmoid(gf);
            float ig = fast_sigmoid(gi);
            float og = fast_sigmoid(go);
            float gt = fast_tanh(gg);
            cval = fg * cval + ig * gt;
            hval = og * fast_tanh(cval);

            out[(size_t)t * BH + (size_t)gb * HID + gj] = hval;
        }

        if (t < S_LEN - 1) {
            // ---- per-bg group barrier: 32 arrivals on one counter ----
            __syncthreads();
            if (tid == 0) {
                asm volatile("red.release.gpu.global.add.u32 [%0], 1;"
                             :: "l"(barp) : "memory");
                unsigned target = (unsigned)(t + 1) * 32u;
                unsigned v;
                do {
                    asm volatile("ld.acquire.gpu.global.u32 %0, [%1];"
                                 : "=r"(v) : "l"(barp) : "memory");
                } while (v < target);
            }
            __syncthreads();
        } else if (is_act) {
            out[(size_t)S_LEN * BH + (size_t)gb * HID + gj] = hval;        // h_f
            out[(size_t)S_LEN * BH + BH + (size_t)gb * HID + gj] = cval;   // c_f
        }
    }
}

// -------------------- launch ------------------------------------------------
extern "C" void kernel_launch(void* const* d_in, const int* in_sizes, int n_in,
                              void* d_out, int out_size)
{
    (void)in_sizes; (void)n_in; (void)out_size;
    const float* x   = (const float*)d_in[0];
    const float* Wxf = (const float*)d_in[1];
    const float* bxf = (const float*)d_in[2];
    const float* Whf = (const float*)d_in[3];
    const float* bhf = (const float*)d_in[4];
    const float* Wxi = (const float*)d_in[5];
    const float* bxi = (const float*)d_in[6];
    const float* Whi = (const float*)d_in[7];
    const float* bhi = (const float*)d_in[8];
    const float* Wxo = (const float*)d_in[9];
    const float* bxo = (const float*)d_in[10];
    const float* Who = (const float*)d_in[11];
    const float* bho = (const float*)d_in[12];
    const float* Wxg = (const float*)d_in[13];
    const float* bxg = (const float*)d_in[14];
    const float* Whg = (const float*)d_in[15];
    const float* bhg = (const float*)d_in[16];
    float* out = (float*)d_out;

    bar_init_kernel<<<1, 128>>>();
    pack_wx_kernel<<<(IN_DIM * G4 + 255) / 256, 256>>>(
        Wxf, Wxi, Wxo, Wxg, bxf, bhf, bxi, bhi, bxo, bho, bxg, bhg);
    pack_wh_kernel<<<(G4 * HID + 255) / 256, 256>>>(Whf, Whi, Who, Whg);

    dim3 gproj(G4 / 128, (S_LEN * BATCH) / 128);
    xproj_kernel<<<gproj, 256>>>(x);

    static bool attr_set = false;
    if (!attr_set) {
        cudaFuncSetAttribute(lstm_rec_kernel,
                             cudaFuncAttributeMaxDynamicSharedMemorySize, REC_SMEM);
        attr_set = true;
    }
    lstm_rec_kernel<<<NCTA, 512, REC_SMEM>>>(out);
}

// round 6
// speedup vs baseline: 1.6264x; 1.6264x over previous
#include <cuda_runtime.h>
#include <cuda_bf16.h>
#include <math.h>

// ---------------------------------------------------------------------------
// LSTM: S=512, B=64, I=256, H=512
// out = [h_seq (S,B,H) | h_final (B,H) | c_final (B,H)]  (fp32)
// ---------------------------------------------------------------------------

#define S_LEN 512
#define BATCH 64
#define IN_DIM 256
#define HID 512
#define G4 2048              // 4*H
#define BH (BATCH*HID)       // 32768
#define BG (BATCH*G4)        // 131072
#define HPAD 516             // padded row stride (floats)
#define NCTA 128
#define PBS 19               // partial-buffer batch stride (floats)
#define PBK (64*PBS)         // per-kq partial block

// -------------------- device scratch (static: no allocs allowed) ------------
__device__ float g_xp[(size_t)S_LEN * BATCH * G4];   // x@Wx + bx + bh
__device__ float g_Wx[IN_DIM * G4];                  // packed (K x 4H)
__device__ float g_WhT[(size_t)G4 * HID];            // WhT[col][k]
__device__ float g_bias[G4];                         // bx + bh
__device__ unsigned int g_barc[4 * 32];              // per-bg counters, 128B apart

// -------------------- f32x2 helpers (Blackwell packed fp32) -----------------
__device__ __forceinline__ void fma2(unsigned long long& d,
                                     unsigned long long a,
                                     unsigned long long b) {
    asm("fma.rn.f32x2 %0, %1, %2, %0;" : "+l"(d) : "l"(a), "l"(b));
}
__device__ __forceinline__ unsigned long long dup2(float a) {
    unsigned long long d;
    asm("mov.b64 %0, {%1, %1};" : "=l"(d) : "f"(a));
    return d;
}
__device__ __forceinline__ float sum2(unsigned long long v) {
    float lo, hi;
    asm("mov.b64 {%0, %1}, %2;" : "=f"(lo), "=f"(hi) : "l"(v));
    return lo + hi;
}

// fast activations: ex2.approx + rcp.approx (rel err ~1e-6, safe vs 1e-3 tol)
__device__ __forceinline__ float fast_exp(float x) {
    float e;
    asm("ex2.approx.f32 %0, %1;" : "=f"(e) : "f"(x * 1.4426950408889634f));
    return e;
}
__device__ __forceinline__ float fast_rcp(float x) {
    float r;
    asm("rcp.approx.f32 %0, %1;" : "=f"(r) : "f"(x));
    return r;
}
__device__ __forceinline__ float fast_sigmoid(float x) {
    return fast_rcp(1.f + fast_exp(-x));
}
__device__ __forceinline__ float fast_tanh(float x) {
    return 2.f * fast_rcp(1.f + fast_exp(-2.f * x)) - 1.f;
}

__device__ __forceinline__ void cpasync16(unsigned dst, const void* src) {
    asm volatile("cp.async.cg.shared.global [%0], [%1], 16;"
                 :: "r"(dst), "l"(src));
}

// -------------------- init / pack kernels -----------------------------------
__global__ void bar_init_kernel() {
    int i = threadIdx.x;
    if (i < 4 * 32) g_barc[i] = 0u;
}

__global__ void pack_wx_kernel(
    const float* __restrict__ Wf, const float* __restrict__ Wi,
    const float* __restrict__ Wo, const float* __restrict__ Wg,
    const float* __restrict__ bxf, const float* __restrict__ bhf,
    const float* __restrict__ bxi, const float* __restrict__ bhi,
    const float* __restrict__ bxo, const float* __restrict__ bho,
    const float* __restrict__ bxg, const float* __restrict__ bhg)
{
    int idx = blockIdx.x * blockDim.x + threadIdx.x;
    if (idx < IN_DIM * G4) {
        int k = idx >> 11;
        int col = idx & 2047;
        int g = col >> 9;
        int jj = col & 511;
        const float* W = (g == 0) ? Wf : (g == 1) ? Wi : (g == 2) ? Wo : Wg;
        g_Wx[idx] = W[k * HID + jj];
    }
    if (idx < G4) {
        int g = idx >> 9, jj = idx & 511;
        const float* bx = (g == 0) ? bxf : (g == 1) ? bxi : (g == 2) ? bxo : bxg;
        const float* bh = (g == 0) ? bhf : (g == 1) ? bhi : (g == 2) ? bho : bhg;
        g_bias[idx] = bx[jj] + bh[jj];
    }
}

__global__ void pack_wh_kernel(
    const float* __restrict__ Wf, const float* __restrict__ Wi,
    const float* __restrict__ Wo, const float* __restrict__ Wg)
{
    int idx = blockIdx.x * blockDim.x + threadIdx.x;
    if (idx < G4 * HID) {
        int col = idx >> 9;
        int k   = idx & 511;
        int g   = col >> 9;
        int jj  = col & 511;
        const float* W = (g == 0) ? Wf : (g == 1) ? Wi : (g == 2) ? Wo : Wg;
        g_WhT[idx] = W[k * HID + jj];   // WhT[col][k] = Wh[k][col]
    }
}

// -------------------- xproj: xp = x @ Wx_cat + bias --------------------------
// M=32768, N=2048, K=256. Block tile 128x64, BK=16, 256 threads, TM=8, TN=4.
__global__ __launch_bounds__(256) void xproj_kernel(const float* __restrict__ x)
{
    __shared__ float As[16][132];
    __shared__ float Bs[16][64];

    const int tid = threadIdx.x;
    const int tx = tid & 15;
    const int ty = tid >> 4;
    const int bm = blockIdx.y * 128;
    const int bn = blockIdx.x * 64;

    unsigned long long acc[8][2];
#pragma unroll
    for (int i = 0; i < 8; i++) { acc[i][0] = 0ull; acc[i][1] = 0ull; }

    const int a_m = tid >> 2;
    const int a_k = (tid & 3) << 2;
    const int b_r = tid >> 4;
    const int b_c = (tid & 15) << 2;

    const float* Aptr = x + (size_t)bm * IN_DIM;

    for (int kt = 0; kt < IN_DIM; kt += 16) {
        float4 av0 = *(const float4*)(Aptr + (size_t)a_m * IN_DIM + kt + a_k);
        float4 av1 = *(const float4*)(Aptr + (size_t)(a_m + 64) * IN_DIM + kt + a_k);
        float4 bv  = *(const float4*)(g_Wx + (size_t)(kt + b_r) * G4 + bn + b_c);

        As[a_k + 0][a_m] = av0.x; As[a_k + 1][a_m] = av0.y;
        As[a_k + 2][a_m] = av0.z; As[a_k + 3][a_m] = av0.w;
        As[a_k + 0][a_m + 64] = av1.x; As[a_k + 1][a_m + 64] = av1.y;
        As[a_k + 2][a_m + 64] = av1.z; As[a_k + 3][a_m + 64] = av1.w;
        *(float4*)&Bs[b_r][b_c] = bv;
        __syncthreads();

#pragma unroll
        for (int kk = 0; kk < 16; kk++) {
            float4 a0 = *(const float4*)&As[kk][ty * 8];
            float4 a1 = *(const float4*)&As[kk][ty * 8 + 4];
            ulonglong2 bb = *(const ulonglong2*)&Bs[kk][tx * 4];
            float av[8] = {a0.x, a0.y, a0.z, a0.w, a1.x, a1.y, a1.z, a1.w};
#pragma unroll
            for (int i = 0; i < 8; i++) {
                unsigned long long ad = dup2(av[i]);
                fma2(acc[i][0], ad, bb.x);
                fma2(acc[i][1], ad, bb.y);
            }
        }
        __syncthreads();
    }

    const int n0 = bn + tx * 4;
    float4 bias = *(const float4*)&g_bias[n0];
#pragma unroll
    for (int i = 0; i < 8; i++) {
        float l0, h0, l1, h1;
        asm("mov.b64 {%0, %1}, %2;" : "=f"(l0), "=f"(h0) : "l"(acc[i][0]));
        asm("mov.b64 {%0, %1}, %2;" : "=f"(l1), "=f"(h1) : "l"(acc[i][1]));
        float4 outv = make_float4(l0 + bias.x, h0 + bias.y, l1 + bias.z, h1 + bias.w);
        int m = bm + ty * 8 + i;
        *(float4*)&g_xp[(size_t)m * G4 + n0] = outv;
    }
}

// -------------------- recurrence: 2-D persistent, group barriers -------------
// 128 CTAs = 4 batch-groups (bg: 16 batches) x 32 unit-groups (ug: 16 units).
// 256 threads, 1 CTA/SM. Dot thread = 4 gate-rows x 4 batches x K/4:
//   kq=tid>>6, rt=(tid>>2)&15, bt=tid&3. Per 16B k-chunk: 8 LDS.128 + 32 FFMA2
//   (FMA:LDS=4:1, 16 independent chains). Smem rows PERMUTED so each w-load
//   instruction hits 8 consecutive slots -> full 128B conflict-free wavefront:
//   wh slot s holds logical gate-row r=(s&15)*4+(s>>4); h slot s holds batch
//   (s&3)*4+(s>>2). k-quarter partials -> pbuf[kq][r][b] (stride 19), summed
//   by activation threads (b,u) which own c in a register.
// Barrier: per-bg red.release counter, 32 arrivals, tid0 polls.
#define REC_SMEM ((80 * HPAD + 4 * PBK) * 4)

__global__ __launch_bounds__(256, 1) void lstm_rec_kernel(float* __restrict__ out)
{
    extern __shared__ float sm[];
    float* h_s  = sm;                  // 16 * HPAD (permuted batch rows)
    float* wh_s = sm + 16 * HPAD;      // 64 * HPAD (permuted gate rows)
    float* pbuf = sm + 80 * HPAD;      // 4 * 64 * PBS

    const int tid = threadIdx.x;
    const int cta = blockIdx.x;
    const int ug  = cta & 31;          // units [ug*16, ug*16+16)
    const int bg  = cta >> 5;          // batches [bg*16, +16)

    // ---- load Wh slice (permuted): slot s <- logical row r=(s&15)*4+(s>>4),
    //      logical row r = gate*16+unit: col=(r>>4)*512 + ug*16 + (r&15) ----
    for (int idx = tid; idx < 64 * 128; idx += 256) {
        int slot = idx >> 7;
        int k4   = (idx & 127) << 2;
        int r    = ((slot & 15) << 2) + (slot >> 4);
        int col  = (r >> 4) * HID + (ug << 4) + (r & 15);
        float4 v = *(const float4*)&g_WhT[(size_t)col * HID + k4];
        *(float4*)&wh_s[slot * HPAD + k4] = v;
    }
    __syncthreads();

    // ---- dot-thread mapping ----
    const int kq = tid >> 6;           // k-quarter: k0 = kq*128
    const int rt = (tid >> 2) & 15;    // row-tile (4 rows)
    const int bt = tid & 3;            // batch-tile (4 batches)

    const ulonglong2* wp0 = (const ulonglong2*)(wh_s + ( 0 + rt) * HPAD + kq * 128);
    const ulonglong2* wp1 = (const ulonglong2*)(wh_s + (16 + rt) * HPAD + kq * 128);
    const ulonglong2* wp2 = (const ulonglong2*)(wh_s + (32 + rt) * HPAD + kq * 128);
    const ulonglong2* wp3 = (const ulonglong2*)(wh_s + (48 + rt) * HPAD + kq * 128);
    const ulonglong2* hp0 = (const ulonglong2*)(h_s + ( 0 + bt) * HPAD + kq * 128);
    const ulonglong2* hp1 = (const ulonglong2*)(h_s + ( 4 + bt) * HPAD + kq * 128);
    const ulonglong2* hp2 = (const ulonglong2*)(h_s + ( 8 + bt) * HPAD + kq * 128);
    const ulonglong2* hp3 = (const ulonglong2*)(h_s + (12 + bt) * HPAD + kq * 128);

    // partial store base: pbuf[kq][rt*4+j][bt*4+l]
    float* pb = pbuf + kq * PBK + (rt << 2) * PBS + (bt << 2);

    // ---- activation-thread mapping: (b,u) ----
    const int ab = tid >> 4;                 // local batch 0..15
    const int au = tid & 15;                 // local unit 0..15
    const int gb = bg * 16 + ab;             // global batch
    const int gj = (ug << 4) + au;           // global hidden unit

    const unsigned hbase = (unsigned)__cvta_generic_to_shared(h_s);
    unsigned int* barp = &g_barc[bg * 32];

    const size_t xof = (size_t)gb * G4 + gj;
    float c0 = g_xp[xof];
    float c1 = g_xp[xof + 512];
    float c2 = g_xp[xof + 1024];
    float c3 = g_xp[xof + 1536];

    float cval = 0.f;

    for (int t = 0; t < S_LEN; t++) {
        if (t > 0) {
            // stage h(t-1)[bg batches] into permuted slots (transpose 4x4 of row)
            const float4* src = (const float4*)(out + (size_t)(t - 1) * BH
                                                + (size_t)(bg * 16) * HID);
#pragma unroll
            for (int i = 0; i < 8; i++) {            // 2048 float4 / 256 thr
                int idx  = tid + (i << 8);
                int row  = idx >> 7;
                int col  = (idx & 127) << 2;
                int slot = ((row & 3) << 2) + (row >> 2);
                cpasync16(hbase + (unsigned)(slot * HPAD + col) * 4u,
                          (const void*)(src + idx));
            }
            asm volatile("cp.async.commit_group;");
            asm volatile("cp.async.wait_group 0;" ::: "memory");
            __syncthreads();
        }

        // prefetch xp for t+1 (hidden under dot loop)
        float n0 = 0.f, n1 = 0.f, n2 = 0.f, n3 = 0.f;
        if (t + 1 < S_LEN) {
            size_t nb = (size_t)(t + 1) * BG + xof;
            n0 = g_xp[nb]; n1 = g_xp[nb + 512];
            n2 = g_xp[nb + 1024]; n3 = g_xp[nb + 1536];
        }

        if (t > 0) {
            unsigned long long acc[4][4];
#pragma unroll
            for (int j = 0; j < 4; j++)
#pragma unroll
                for (int l = 0; l < 4; l++) acc[j][l] = 0ull;

#pragma unroll 4
            for (int k = 0; k < 32; k++) {
                ulonglong2 w0v = wp0[k];
                ulonglong2 w1v = wp1[k];
                ulonglong2 w2v = wp2[k];
                ulonglong2 w3v = wp3[k];
                ulonglong2 h0v = hp0[k];
                ulonglong2 h1v = hp1[k];
                ulonglong2 h2v = hp2[k];
                ulonglong2 h3v = hp3[k];

                fma2(acc[0][0], h0v.x, w0v.x); fma2(acc[0][0], h0v.y, w0v.y);
                fma2(acc[0][1], h1v.x, w0v.x); fma2(acc[0][1], h1v.y, w0v.y);
                fma2(acc[0][2], h2v.x, w0v.x); fma2(acc[0][2], h2v.y, w0v.y);
                fma2(acc[0][3], h3v.x, w0v.x); fma2(acc[0][3], h3v.y, w0v.y);
                fma2(acc[1][0], h0v.x, w1v.x); fma2(acc[1][0], h0v.y, w1v.y);
                fma2(acc[1][1], h1v.x, w1v.x); fma2(acc[1][1], h1v.y, w1v.y);
                fma2(acc[1][2], h2v.x, w1v.x); fma2(acc[1][2], h2v.y, w1v.y);
                fma2(acc[1][3], h3v.x, w1v.x); fma2(acc[1][3], h3v.y, w1v.y);
                fma2(acc[2][0], h0v.x, w2v.x); fma2(acc[2][0], h0v.y, w2v.y);
                fma2(acc[2][1], h1v.x, w2v.x); fma2(acc[2][1], h1v.y, w2v.y);
                fma2(acc[2][2], h2v.x, w2v.x); fma2(acc[2][2], h2v.y, w2v.y);
                fma2(acc[2][3], h3v.x, w2v.x); fma2(acc[2][3], h3v.y, w2v.y);
                fma2(acc[3][0], h0v.x, w3v.x); fma2(acc[3][0], h0v.y, w3v.y);
                fma2(acc[3][1], h1v.x, w3v.x); fma2(acc[3][1], h1v.y, w3v.y);
                fma2(acc[3][2], h2v.x, w3v.x); fma2(acc[3][2], h2v.y, w3v.y);
                fma2(acc[3][3], h3v.x, w3v.x); fma2(acc[3][3], h3v.y, w3v.y);
            }

            // wh slot (j*16+rt) holds logical row rt*4+j; h slot (l*4+bt)
            // holds logical batch bt*4+l -> pbuf[kq][rt*4+j][bt*4+l]
#pragma unroll
            for (int j = 0; j < 4; j++)
#pragma unroll
                for (int l = 0; l < 4; l++)
                    pb[j * PBS + l] = sum2(acc[j][l]);
            __syncthreads();
        }

        // ---- activation: thread (ab, au) ----
        float gf = c0, gi = c1, go = c2, gg = c3;
        if (t > 0) {
#pragma unroll
            for (int q = 0; q < 4; q++) {
                const float* p = pbuf + q * PBK + ab;
                gf += p[(au +  0) * PBS];
                gi += p[(au + 16) * PBS];
                go += p[(au + 32) * PBS];
                gg += p[(au + 48) * PBS];
            }
        }
        c0 = n0; c1 = n1; c2 = n2; c3 = n3;

        float fg = fast_sigmoid(gf);
        float ig = fast_sigmoid(gi);
        float og = fast_sigmoid(go);
        float gt = fast_tanh(gg);
        cval = fg * cval + ig * gt;
        float hval = og * fast_tanh(cval);

        out[(size_t)t * BH + (size_t)gb * HID + gj] = hval;

        if (t < S_LEN - 1) {
            // ---- per-bg group barrier: 32 arrivals on one counter ----
            __syncthreads();
            if (tid == 0) {
                asm volatile("red.release.gpu.global.add.u32 [%0], 1;"
                             :: "l"(barp) : "memory");
                unsigned target = (unsigned)(t + 1) * 32u;
                unsigned v;
                while (true) {
                    asm volatile("ld.acquire.gpu.global.u32 %0, [%1];"
                                 : "=r"(v) : "l"(barp) : "memory");
                    if (v >= target) break;
                    __nanosleep(20);
                }
            }
            __syncthreads();
        } else {
            out[(size_t)S_LEN * BH + (size_t)gb * HID + gj] = hval;        // h_f
            out[(size_t)S_LEN * BH + BH + (size_t)gb * HID + gj] = cval;   // c_f
        }
    }
}

// -------------------- launch ------------------------------------------------
extern "C" void kernel_launch(void* const* d_in, const int* in_sizes, int n_in,
                              void* d_out, int out_size)
{
    (void)in_sizes; (void)n_in; (void)out_size;
    const float* x   = (const float*)d_in[0];
    const float* Wxf = (const float*)d_in[1];
    const float* bxf = (const float*)d_in[2];
    const float* Whf = (const float*)d_in[3];
    const float* bhf = (const float*)d_in[4];
    const float* Wxi = (const float*)d_in[5];
    const float* bxi = (const float*)d_in[6];
    const float* Whi = (const float*)d_in[7];
    const float* bhi = (const float*)d_in[8];
    const float* Wxo = (const float*)d_in[9];
    const float* bxo = (const float*)d_in[10];
    const float* Who = (const float*)d_in[11];
    const float* bho = (const float*)d_in[12];
    const float* Wxg = (const float*)d_in[13];
    const float* bxg = (const float*)d_in[14];
    const float* Whg = (const float*)d_in[15];
    const float* bhg = (const float*)d_in[16];
    float* out = (float*)d_out;

    bar_init_kernel<<<1, 128>>>();
    pack_wx_kernel<<<(IN_DIM * G4 + 255) / 256, 256>>>(
        Wxf, Wxi, Wxo, Wxg, bxf, bhf, bxi, bhi, bxo, bho, bxg, bhg);
    pack_wh_kernel<<<(G4 * HID + 255) / 256, 256>>>(Whf, Whi, Who, Whg);

    dim3 gproj(G4 / 64, (S_LEN * BATCH) / 128);
    xproj_kernel<<<gproj, 256>>>(x);

    static bool attr_set = false;
    if (!attr_set) {
        cudaFuncSetAttribute(lstm_rec_kernel,
                             cudaFuncAttributeMaxDynamicSharedMemorySize, REC_SMEM);
        attr_set = true;
    }
    lstm_rec_kernel<<<NCTA, 256, REC_SMEM>>>(out);
}

// round 7
// speedup vs baseline: 1.6639x; 1.0231x over previous
#include <cuda_runtime.h>
#include <cuda_bf16.h>
#include <math.h>

// ---------------------------------------------------------------------------
// LSTM: S=512, B=64, I=256, H=512
// out = [h_seq (S,B,H) | h_final (B,H) | c_final (B,H)]  (fp32)
// ---------------------------------------------------------------------------

#define S_LEN 512
#define BATCH 64
#define IN_DIM 256
#define HID 512
#define G4 2048              // 4*H
#define BH (BATCH*HID)       // 32768
#define BG (BATCH*G4)        // 131072
#define HPAD 516             // padded row stride (floats)
#define NCTA 128
#define PBS 19               // partial-buffer batch stride (floats)
#define PBK (64*PBS)         // per-kq partial block

// -------------------- device scratch (static: no allocs allowed) ------------
__device__ float g_xp[(size_t)S_LEN * BATCH * G4];   // x@Wx + bx + bh
__device__ float g_Wx[IN_DIM * G4];                  // packed (K x 4H)
__device__ float g_WhT[(size_t)G4 * HID];            // WhT[col][k]
__device__ float g_bias[G4];                         // bx + bh
__device__ unsigned int g_barc[4 * 32];              // per-bg counters, 128B apart

// -------------------- f32x2 helpers (Blackwell packed fp32) -----------------
__device__ __forceinline__ void fma2(unsigned long long& d,
                                     unsigned long long a,
                                     unsigned long long b) {
    asm("fma.rn.f32x2 %0, %1, %2, %0;" : "+l"(d) : "l"(a), "l"(b));
}
__device__ __forceinline__ unsigned long long dup2(float a) {
    unsigned long long d;
    asm("mov.b64 %0, {%1, %1};" : "=l"(d) : "f"(a));
    return d;
}
__device__ __forceinline__ float sum2(unsigned long long v) {
    float lo, hi;
    asm("mov.b64 {%0, %1}, %2;" : "=f"(lo), "=f"(hi) : "l"(v));
    return lo + hi;
}

// fast activations: ex2.approx + rcp.approx (rel err ~1e-6, safe vs 1e-3 tol)
__device__ __forceinline__ float fast_exp(float x) {
    float e;
    asm("ex2.approx.f32 %0, %1;" : "=f"(e) : "f"(x * 1.4426950408889634f));
    return e;
}
__device__ __forceinline__ float fast_rcp(float x) {
    float r;
    asm("rcp.approx.f32 %0, %1;" : "=f"(r) : "f"(x));
    return r;
}
__device__ __forceinline__ float fast_sigmoid(float x) {
    return fast_rcp(1.f + fast_exp(-x));
}
__device__ __forceinline__ float fast_tanh(float x) {
    return 2.f * fast_rcp(1.f + fast_exp(-2.f * x)) - 1.f;
}

__device__ __forceinline__ void cpasync16(unsigned dst, const void* src) {
    asm volatile("cp.async.cg.shared.global [%0], [%1], 16;"
                 :: "r"(dst), "l"(src));
}

// -------------------- merged prep kernel (1 launch) --------------------------
// Covers: barrier reset, bias pack, Wx pack, WhT pack. Grid 4096 x 256.
__global__ void prep_kernel(
    const float* __restrict__ Wxf, const float* __restrict__ Wxi,
    const float* __restrict__ Wxo, const float* __restrict__ Wxg,
    const float* __restrict__ Whf, const float* __restrict__ Whi,
    const float* __restrict__ Who, const float* __restrict__ Whg,
    const float* __restrict__ bxf, const float* __restrict__ bhf,
    const float* __restrict__ bxi, const float* __restrict__ bhi,
    const float* __restrict__ bxo, const float* __restrict__ bho,
    const float* __restrict__ bxg, const float* __restrict__ bhg)
{
    int idx = blockIdx.x * blockDim.x + threadIdx.x;

    if (idx < 4 * 32) g_barc[idx] = 0u;

    if (idx < G4) {
        int g = idx >> 9, jj = idx & 511;
        const float* bx = (g == 0) ? bxf : (g == 1) ? bxi : (g == 2) ? bxo : bxg;
        const float* bh = (g == 0) ? bhf : (g == 1) ? bhi : (g == 2) ? bho : bhg;
        g_bias[idx] = bx[jj] + bh[jj];
    }

    if (idx < IN_DIM * G4) {
        int k = idx >> 11;
        int col = idx & 2047;
        int g = col >> 9;
        int jj = col & 511;
        const float* W = (g == 0) ? Wxf : (g == 1) ? Wxi : (g == 2) ? Wxo : Wxg;
        g_Wx[idx] = W[k * HID + jj];
    }

    if (idx < G4 * HID) {
        int col = idx >> 9;
        int k   = idx & 511;
        int g   = col >> 9;
        int jj  = col & 511;
        const float* W = (g == 0) ? Whf : (g == 1) ? Whi : (g == 2) ? Who : Whg;
        g_WhT[idx] = W[k * HID + jj];   // WhT[col][k] = Wh[k][col]
    }
}

// -------------------- xproj: xp = x @ Wx_cat + bias --------------------------
// M=32768, N=2048, K=256. Tile 128x64, BK=16, 256 threads, TM=8, TN=4.
// 2-stage smem double buffer, 1 syncthreads/iter; next tile's LDGs issued
// before compute so L2/DRAM latency hides under the FFMA2 block.
__global__ __launch_bounds__(256) void xproj_kernel(const float* __restrict__ x)
{
    __shared__ float As[2][16][132];   // transposed A tile, padded
    __shared__ float Bs[2][16][64];

    const int tid = threadIdx.x;
    const int tx = tid & 15;
    const int ty = tid >> 4;
    const int bm = blockIdx.y * 128;
    const int bn = blockIdx.x * 64;

    unsigned long long acc[8][2];
#pragma unroll
    for (int i = 0; i < 8; i++) { acc[i][0] = 0ull; acc[i][1] = 0ull; }

    const int a_m = tid >> 2;
    const int a_k = (tid & 3) << 2;
    const int b_r = tid >> 4;
    const int b_c = (tid & 15) << 2;

    const float* Aptr = x + (size_t)bm * IN_DIM;

    // prologue: load tile 0 and store to buffer 0
    {
        float4 av0 = *(const float4*)(Aptr + (size_t)a_m * IN_DIM + a_k);
        float4 av1 = *(const float4*)(Aptr + (size_t)(a_m + 64) * IN_DIM + a_k);
        float4 bv  = *(const float4*)(g_Wx + (size_t)b_r * G4 + bn + b_c);
        As[0][a_k + 0][a_m] = av0.x; As[0][a_k + 1][a_m] = av0.y;
        As[0][a_k + 2][a_m] = av0.z; As[0][a_k + 3][a_m] = av0.w;
        As[0][a_k + 0][a_m + 64] = av1.x; As[0][a_k + 1][a_m + 64] = av1.y;
        As[0][a_k + 2][a_m + 64] = av1.z; As[0][a_k + 3][a_m + 64] = av1.w;
        *(float4*)&Bs[0][b_r][b_c] = bv;
    }
    __syncthreads();

#pragma unroll
    for (int kt = 0; kt < IN_DIM; kt += 16) {
        const int p = (kt >> 4) & 1;
        const bool has_next = (kt + 16) < IN_DIM;

        float4 nav0, nav1, nbv;
        if (has_next) {
            nav0 = *(const float4*)(Aptr + (size_t)a_m * IN_DIM + kt + 16 + a_k);
            nav1 = *(const float4*)(Aptr + (size_t)(a_m + 64) * IN_DIM + kt + 16 + a_k);
            nbv  = *(const float4*)(g_Wx + (size_t)(kt + 16 + b_r) * G4 + bn + b_c);
        }

#pragma unroll
        for (int kk = 0; kk < 16; kk++) {
            float4 a0 = *(const float4*)&As[p][kk][ty * 8];
            float4 a1 = *(const float4*)&As[p][kk][ty * 8 + 4];
            ulonglong2 bb = *(const ulonglong2*)&Bs[p][kk][tx * 4];
            float av[8] = {a0.x, a0.y, a0.z, a0.w, a1.x, a1.y, a1.z, a1.w};
#pragma unroll
            for (int i = 0; i < 8; i++) {
                unsigned long long ad = dup2(av[i]);
                fma2(acc[i][0], ad, bb.x);
                fma2(acc[i][1], ad, bb.y);
            }
        }

        if (has_next) {
            const int q = p ^ 1;
            As[q][a_k + 0][a_m] = nav0.x; As[q][a_k + 1][a_m] = nav0.y;
            As[q][a_k + 2][a_m] = nav0.z; As[q][a_k + 3][a_m] = nav0.w;
            As[q][a_k + 0][a_m + 64] = nav1.x; As[q][a_k + 1][a_m + 64] = nav1.y;
            As[q][a_k + 2][a_m + 64] = nav1.z; As[q][a_k + 3][a_m + 64] = nav1.w;
            *(float4*)&Bs[q][b_r][b_c] = nbv;
            __syncthreads();
        }
    }

    const int n0 = bn + tx * 4;
    float4 bias = *(const float4*)&g_bias[n0];
#pragma unroll
    for (int i = 0; i < 8; i++) {
        float l0, h0, l1, h1;
        asm("mov.b64 {%0, %1}, %2;" : "=f"(l0), "=f"(h0) : "l"(acc[i][0]));
        asm("mov.b64 {%0, %1}, %2;" : "=f"(l1), "=f"(h1) : "l"(acc[i][1]));
        float4 outv = make_float4(l0 + bias.x, h0 + bias.y, l1 + bias.z, h1 + bias.w);
        int m = bm + ty * 8 + i;
        *(float4*)&g_xp[(size_t)m * G4 + n0] = outv;
    }
}

// -------------------- recurrence: 2-D persistent, group barriers -------------
// (unchanged from R6 — protecting the win)
#define REC_SMEM ((80 * HPAD + 4 * PBK) * 4)

__global__ __launch_bounds__(256, 1) void lstm_rec_kernel(float* __restrict__ out)
{
    extern __shared__ float sm[];
    float* h_s  = sm;                  // 16 * HPAD (permuted batch rows)
    float* wh_s = sm + 16 * HPAD;      // 64 * HPAD (permuted gate rows)
    float* pbuf = sm + 80 * HPAD;      // 4 * 64 * PBS

    const int tid = threadIdx.x;
    const int cta = blockIdx.x;
    const int ug  = cta & 31;          // units [ug*16, ug*16+16)
    const int bg  = cta >> 5;          // batches [bg*16, +16)

    for (int idx = tid; idx < 64 * 128; idx += 256) {
        int slot = idx >> 7;
        int k4   = (idx & 127) << 2;
        int r    = ((slot & 15) << 2) + (slot >> 4);
        int col  = (r >> 4) * HID + (ug << 4) + (r & 15);
        float4 v = *(const float4*)&g_WhT[(size_t)col * HID + k4];
        *(float4*)&wh_s[slot * HPAD + k4] = v;
    }
    __syncthreads();

    const int kq = tid >> 6;
    const int rt = (tid >> 2) & 15;
    const int bt = tid & 3;

    const ulonglong2* wp0 = (const ulonglong2*)(wh_s + ( 0 + rt) * HPAD + kq * 128);
    const ulonglong2* wp1 = (const ulonglong2*)(wh_s + (16 + rt) * HPAD + kq * 128);
    const ulonglong2* wp2 = (const ulonglong2*)(wh_s + (32 + rt) * HPAD + kq * 128);
    const ulonglong2* wp3 = (const ulonglong2*)(wh_s + (48 + rt) * HPAD + kq * 128);
    const ulonglong2* hp0 = (const ulonglong2*)(h_s + ( 0 + bt) * HPAD + kq * 128);
    const ulonglong2* hp1 = (const ulonglong2*)(h_s + ( 4 + bt) * HPAD + kq * 128);
    const ulonglong2* hp2 = (const ulonglong2*)(h_s + ( 8 + bt) * HPAD + kq * 128);
    const ulonglong2* hp3 = (const ulonglong2*)(h_s + (12 + bt) * HPAD + kq * 128);

    float* pb = pbuf + kq * PBK + (rt << 2) * PBS + (bt << 2);

    const int ab = tid >> 4;
    const int au = tid & 15;
    const int gb = bg * 16 + ab;
    const int gj = (ug << 4) + au;

    const unsigned hbase = (unsigned)__cvta_generic_to_shared(h_s);
    unsigned int* barp = &g_barc[bg * 32];

    const size_t xof = (size_t)gb * G4 + gj;
    float c0 = g_xp[xof];
    float c1 = g_xp[xof + 512];
    float c2 = g_xp[xof + 1024];
    float c3 = g_xp[xof + 1536];

    float cval = 0.f;

    for (int t = 0; t < S_LEN; t++) {
        if (t > 0) {
            const float4* src = (const float4*)(out + (size_t)(t - 1) * BH
                                                + (size_t)(bg * 16) * HID);
#pragma unroll
            for (int i = 0; i < 8; i++) {
                int idx  = tid + (i << 8);
                int row  = idx >> 7;
                int col  = (idx & 127) << 2;
                int slot = ((row & 3) << 2) + (row >> 2);
                cpasync16(hbase + (unsigned)(slot * HPAD + col) * 4u,
                          (const void*)(src + idx));
            }
            asm volatile("cp.async.commit_group;");
            asm volatile("cp.async.wait_group 0;" ::: "memory");
            __syncthreads();
        }

        float n0 = 0.f, n1 = 0.f, n2 = 0.f, n3 = 0.f;
        if (t + 1 < S_LEN) {
            size_t nb = (size_t)(t + 1) * BG + xof;
            n0 = g_xp[nb]; n1 = g_xp[nb + 512];
            n2 = g_xp[nb + 1024]; n3 = g_xp[nb + 1536];
        }

        if (t > 0) {
            unsigned long long acc[4][4];
#pragma unroll
            for (int j = 0; j < 4; j++)
#pragma unroll
                for (int l = 0; l < 4; l++) acc[j][l] = 0ull;

#pragma unroll 4
            for (int k = 0; k < 32; k++) {
                ulonglong2 w0v = wp0[k];
                ulonglong2 w1v = wp1[k];
                ulonglong2 w2v = wp2[k];
                ulonglong2 w3v = wp3[k];
                ulonglong2 h0v = hp0[k];
                ulonglong2 h1v = hp1[k];
                ulonglong2 h2v = hp2[k];
                ulonglong2 h3v = hp3[k];

                fma2(acc[0][0], h0v.x, w0v.x); fma2(acc[0][0], h0v.y, w0v.y);
                fma2(acc[0][1], h1v.x, w0v.x); fma2(acc[0][1], h1v.y, w0v.y);
                fma2(acc[0][2], h2v.x, w0v.x); fma2(acc[0][2], h2v.y, w0v.y);
                fma2(acc[0][3], h3v.x, w0v.x); fma2(acc[0][3], h3v.y, w0v.y);
                fma2(acc[1][0], h0v.x, w1v.x); fma2(acc[1][0], h0v.y, w1v.y);
                fma2(acc[1][1], h1v.x, w1v.x); fma2(acc[1][1], h1v.y, w1v.y);
                fma2(acc[1][2], h2v.x, w1v.x); fma2(acc[1][2], h2v.y, w1v.y);
                fma2(acc[1][3], h3v.x, w1v.x); fma2(acc[1][3], h3v.y, w1v.y);
                fma2(acc[2][0], h0v.x, w2v.x); fma2(acc[2][0], h0v.y, w2v.y);
                fma2(acc[2][1], h1v.x, w2v.x); fma2(acc[2][1], h1v.y, w2v.y);
                fma2(acc[2][2], h2v.x, w2v.x); fma2(acc[2][2], h2v.y, w2v.y);
                fma2(acc[2][3], h3v.x, w2v.x); fma2(acc[2][3], h3v.y, w2v.y);
                fma2(acc[3][0], h0v.x, w3v.x); fma2(acc[3][0], h0v.y, w3v.y);
                fma2(acc[3][1], h1v.x, w3v.x); fma2(acc[3][1], h1v.y, w3v.y);
                fma2(acc[3][2], h2v.x, w3v.x); fma2(acc[3][2], h2v.y, w3v.y);
                fma2(acc[3][3], h3v.x, w3v.x); fma2(acc[3][3], h3v.y, w3v.y);
            }

#pragma unroll
            for (int j = 0; j < 4; j++)
#pragma unroll
                for (int l = 0; l < 4; l++)
                    pb[j * PBS + l] = sum2(acc[j][l]);
            __syncthreads();
        }

        float gf = c0, gi = c1, go = c2, gg = c3;
        if (t > 0) {
#pragma unroll
            for (int q = 0; q < 4; q++) {
                const float* p = pbuf + q * PBK + ab;
                gf += p[(au +  0) * PBS];
                gi += p[(au + 16) * PBS];
                go += p[(au + 32) * PBS];
                gg += p[(au + 48) * PBS];
            }
        }
        c0 = n0; c1 = n1; c2 = n2; c3 = n3;

        float fg = fast_sigmoid(gf);
        float ig = fast_sigmoid(gi);
        float og = fast_sigmoid(go);
        float gt = fast_tanh(gg);
        cval = fg * cval + ig * gt;
        float hval = og * fast_tanh(cval);

        out[(size_t)t * BH + (size_t)gb * HID + gj] = hval;

        if (t < S_LEN - 1) {
            __syncthreads();
            if (tid == 0) {
                asm volatile("red.release.gpu.global.add.u32 [%0], 1;"
                             :: "l"(barp) : "memory");
                unsigned target = (unsigned)(t + 1) * 32u;
                unsigned v;
                while (true) {
                    asm volatile("ld.acquire.gpu.global.u32 %0, [%1];"
                                 : "=r"(v) : "l"(barp) : "memory");
                    if (v >= target) break;
                    __nanosleep(20);
                }
            }
            __syncthreads();
        } else {
            out[(size_t)S_LEN * BH + (size_t)gb * HID + gj] = hval;        // h_f
            out[(size_t)S_LEN * BH + BH + (size_t)gb * HID + gj] = cval;   // c_f
        }
    }
}

// -------------------- launch ------------------------------------------------
extern "C" void kernel_launch(void* const* d_in, const int* in_sizes, int n_in,
                              void* d_out, int out_size)
{
    (void)in_sizes; (void)n_in; (void)out_size;
    const float* x   = (const float*)d_in[0];
    const float* Wxf = (const float*)d_in[1];
    const float* bxf = (const float*)d_in[2];
    const float* Whf = (const float*)d_in[3];
    const float* bhf = (const float*)d_in[4];
    const float* Wxi = (const float*)d_in[5];
    const float* bxi = (const float*)d_in[6];
    const float* Whi = (const float*)d_in[7];
    const float* bhi = (const float*)d_in[8];
    const float* Wxo = (const float*)d_in[9];
    const float* bxo = (const float*)d_in[10];
    const float* Who = (const float*)d_in[11];
    const float* bho = (const float*)d_in[12];
    const float* Wxg = (const float*)d_in[13];
    const float* bxg = (const float*)d_in[14];
    const float* Whg = (const float*)d_in[15];
    const float* bhg = (const float*)d_in[16];
    float* out = (float*)d_out;

    prep_kernel<<<(G4 * HID + 255) / 256, 256>>>(
        Wxf, Wxi, Wxo, Wxg, Whf, Whi, Who, Whg,
        bxf, bhf, bxi, bhi, bxo, bho, bxg, bhg);

    dim3 gproj(G4 / 64, (S_LEN * BATCH) / 128);
    xproj_kernel<<<gproj, 256>>>(x);

    static bool attr_set = false;
    if (!attr_set) {
        cudaFuncSetAttribute(lstm_rec_kernel,
                             cudaFuncAttributeMaxDynamicSharedMemorySize, REC_SMEM);
        attr_set = true;
    }
    lstm_rec_kernel<<<NCTA, 256, REC_SMEM>>>(out);
}

// round 9
// speedup vs baseline: 2.7781x; 1.6696x over previous
#include <cuda_runtime.h>
#include <cuda_bf16.h>
#include <cuda_fp16.h>
#include <math.h>

// ---------------------------------------------------------------------------
// LSTM: S=512, B=64, I=256, H=512
// out = [h_seq (S,B,H) | h_final (B,H) | c_final (B,H)]  (fp32)
// Recurrence: persistent kernel, mma.sync m16n8k16 (W fp16 in REGISTERS,
// h as fp16 hi+lo 2-pass), fp32 activations.
// ---------------------------------------------------------------------------

#define S_LEN 512
#define BATCH 64
#define IN_DIM 256
#define HID 512
#define G4 2048              // 4*H
#define BH (BATCH*HID)       // 32768
#define BG (BATCH*G4)        // 131072
#define NCTA 128
#define BST 520              // B smem row stride (halves): banks 4n+t -> clean

// -------------------- device scratch (static: no allocs allowed) ------------
__device__ float  g_xp[(size_t)S_LEN * BATCH * G4];  // x@Wx + bx + bh
__device__ float  g_Wx[IN_DIM * G4];                 // packed (K x 4H)
__device__ float  g_WhT[(size_t)G4 * HID];           // WhT[col][k]
__device__ float  g_bias[G4];                        // bx + bh
__device__ __half g_hh[2][BH];                       // h hi fp16, ping-pong
__device__ __half g_hl[2][BH];                       // h lo fp16, ping-pong
__device__ unsigned int g_barc[4 * 32];              // per-bg counters

// -------------------- f32x2 helpers ------------------------------------------
__device__ __forceinline__ void fma2(unsigned long long& d,
                                     unsigned long long a,
                                     unsigned long long b) {
    asm("fma.rn.f32x2 %0, %1, %2, %0;" : "+l"(d) : "l"(a), "l"(b));
}
__device__ __forceinline__ unsigned long long dup2(float a) {
    unsigned long long d;
    asm("mov.b64 %0, {%1, %1};" : "=l"(d) : "f"(a));
    return d;
}

// fast activations
__device__ __forceinline__ float fast_exp(float x) {
    float e;
    asm("ex2.approx.f32 %0, %1;" : "=f"(e) : "f"(x * 1.4426950408889634f));
    return e;
}
__device__ __forceinline__ float fast_rcp(float x) {
    float r;
    asm("rcp.approx.f32 %0, %1;" : "=f"(r) : "f"(x));
    return r;
}
__device__ __forceinline__ float fast_sigmoid(float x) {
    return fast_rcp(1.f + fast_exp(-x));
}
__device__ __forceinline__ float fast_tanh(float x) {
    return 2.f * fast_rcp(1.f + fast_exp(-2.f * x)) - 1.f;
}

__device__ __forceinline__ void cpasync16(unsigned dst, const void* src) {
    asm volatile("cp.async.cg.shared.global [%0], [%1], 16;"
                 :: "r"(dst), "l"(src));
}

// mma.sync m16n8k16 row.col f32.f16.f16.f32 (accumulate in place)
__device__ __forceinline__ void hmma16816(float& d0, float& d1, float& d2, float& d3,
                                          unsigned a0, unsigned a1, unsigned a2, unsigned a3,
                                          unsigned b0, unsigned b1) {
    asm volatile(
        "mma.sync.aligned.m16n8k16.row.col.f32.f16.f16.f32 "
        "{%0,%1,%2,%3}, {%4,%5,%6,%7}, {%8,%9}, {%0,%1,%2,%3};"
        : "+f"(d0), "+f"(d1), "+f"(d2), "+f"(d3)
        : "r"(a0), "r"(a1), "r"(a2), "r"(a3), "r"(b0), "r"(b1));
}

// -------------------- merged prep kernel --------------------------------------
__global__ void prep_kernel(
    const float* __restrict__ Wxf, const float* __restrict__ Wxi,
    const float* __restrict__ Wxo, const float* __restrict__ Wxg,
    const float* __restrict__ Whf, const float* __restrict__ Whi,
    const float* __restrict__ Who, const float* __restrict__ Whg,
    const float* __restrict__ bxf, const float* __restrict__ bhf,
    const float* __restrict__ bxi, const float* __restrict__ bhi,
    const float* __restrict__ bxo, const float* __restrict__ bho,
    const float* __restrict__ bxg, const float* __restrict__ bhg)
{
    int idx = blockIdx.x * blockDim.x + threadIdx.x;

    if (idx < 4 * 32) g_barc[idx] = 0u;

    if (idx < G4) {
        int g = idx >> 9, jj = idx & 511;
        const float* bx = (g == 0) ? bxf : (g == 1) ? bxi : (g == 2) ? bxo : bxg;
        const float* bh = (g == 0) ? bhf : (g == 1) ? bhi : (g == 2) ? bho : bhg;
        g_bias[idx] = bx[jj] + bh[jj];
    }

    if (idx < IN_DIM * G4) {
        int k = idx >> 11;
        int col = idx & 2047;
        int g = col >> 9;
        int jj = col & 511;
        const float* W = (g == 0) ? Wxf : (g == 1) ? Wxi : (g == 2) ? Wxo : Wxg;
        g_Wx[idx] = W[k * HID + jj];
    }

    if (idx < G4 * HID) {
        int col = idx >> 9;
        int k   = idx & 511;
        int g   = col >> 9;
        int jj  = col & 511;
        const float* W = (g == 0) ? Whf : (g == 1) ? Whi : (g == 2) ? Who : Whg;
        g_WhT[idx] = W[k * HID + jj];   // WhT[col][k] = Wh[k][col]
    }
}

// -------------------- xproj (unchanged R7) ------------------------------------
__global__ __launch_bounds__(256) void xproj_kernel(const float* __restrict__ x)
{
    __shared__ float As[2][16][132];
    __shared__ float Bs[2][16][64];

    const int tid = threadIdx.x;
    const int tx = tid & 15;
    const int ty = tid >> 4;
    const int bm = blockIdx.y * 128;
    const int bn = blockIdx.x * 64;

    unsigned long long acc[8][2];
#pragma unroll
    for (int i = 0; i < 8; i++) { acc[i][0] = 0ull; acc[i][1] = 0ull; }

    const int a_m = tid >> 2;
    const int a_k = (tid & 3) << 2;
    const int b_r = tid >> 4;
    const int b_c = (tid & 15) << 2;

    const float* Aptr = x + (size_t)bm * IN_DIM;

    {
        float4 av0 = *(const float4*)(Aptr + (size_t)a_m * IN_DIM + a_k);
        float4 av1 = *(const float4*)(Aptr + (size_t)(a_m + 64) * IN_DIM + a_k);
        float4 bv  = *(const float4*)(g_Wx + (size_t)b_r * G4 + bn + b_c);
        As[0][a_k + 0][a_m] = av0.x; As[0][a_k + 1][a_m] = av0.y;
        As[0][a_k + 2][a_m] = av0.z; As[0][a_k + 3][a_m] = av0.w;
        As[0][a_k + 0][a_m + 64] = av1.x; As[0][a_k + 1][a_m + 64] = av1.y;
        As[0][a_k + 2][a_m + 64] = av1.z; As[0][a_k + 3][a_m + 64] = av1.w;
        *(float4*)&Bs[0][b_r][b_c] = bv;
    }
    __syncthreads();

#pragma unroll
    for (int kt = 0; kt < IN_DIM; kt += 16) {
        const int p = (kt >> 4) & 1;
        const bool has_next = (kt + 16) < IN_DIM;

        float4 nav0, nav1, nbv;
        if (has_next) {
            nav0 = *(const float4*)(Aptr + (size_t)a_m * IN_DIM + kt + 16 + a_k);
            nav1 = *(const float4*)(Aptr + (size_t)(a_m + 64) * IN_DIM + kt + 16 + a_k);
            nbv  = *(const float4*)(g_Wx + (size_t)(kt + 16 + b_r) * G4 + bn + b_c);
        }

#pragma unroll
        for (int kk = 0; kk < 16; kk++) {
            float4 a0 = *(const float4*)&As[p][kk][ty * 8];
            float4 a1 = *(const float4*)&As[p][kk][ty * 8 + 4];
            ulonglong2 bb = *(const ulonglong2*)&Bs[p][kk][tx * 4];
            float av[8] = {a0.x, a0.y, a0.z, a0.w, a1.x, a1.y, a1.z, a1.w};
#pragma unroll
            for (int i = 0; i < 8; i++) {
                unsigned long long ad = dup2(av[i]);
                fma2(acc[i][0], ad, bb.x);
                fma2(acc[i][1], ad, bb.y);
            }
        }

        if (has_next) {
            const int q = p ^ 1;
            As[q][a_k + 0][a_m] = nav0.x; As[q][a_k + 1][a_m] = nav0.y;
            As[q][a_k + 2][a_m] = nav0.z; As[q][a_k + 3][a_m] = nav0.w;
            As[q][a_k + 0][a_m + 64] = nav1.x; As[q][a_k + 1][a_m + 64] = nav1.y;
            As[q][a_k + 2][a_m + 64] = nav1.z; As[q][a_k + 3][a_m + 64] = nav1.w;
            *(float4*)&Bs[q][b_r][b_c] = nbv;
            __syncthreads();
        }
    }

    const int n0 = bn + tx * 4;
    float4 bias = *(const float4*)&g_bias[n0];
#pragma unroll
    for (int i = 0; i < 8; i++) {
        float l0, h0, l1, h1;
        asm("mov.b64 {%0, %1}, %2;" : "=f"(l0), "=f"(h0) : "l"(acc[i][0]));
        asm("mov.b64 {%0, %1}, %2;" : "=f"(l1), "=f"(h1) : "l"(acc[i][1]));
        float4 outv = make_float4(l0 + bias.x, h0 + bias.y, l1 + bias.z, h1 + bias.w);
        int m = bm + ty * 8 + i;
        *(float4*)&g_xp[(size_t)m * G4 + n0] = outv;
    }
}

// -------------------- recurrence: mma.sync persistent --------------------------
// 128 CTAs = 4 bg (16 batches) x 32 ug (16 units). 256 threads = 8 warps.
// D[64 gate-rows, 16 batches] = Wh_slice[64 x 512] * h[16 x 512]^T.
// Warp w: m-tile mt=w>>1 (rows mt*16..+15), n-tile nt=w&1 (batches nt*8..+7).
// A (W fp16) in registers: 32 ksteps x 4 b32, loaded ONCE. B (h hi/lo fp16)
// staged per step via cp.async; frags via conflict-free LDS.32.
__global__ __launch_bounds__(256, 1) void lstm_rec_kernel(float* __restrict__ out)
{
    __shared__ __align__(16) __half b_hi[16 * BST];
    __shared__ __align__(16) __half b_lo[16 * BST];
    __shared__ float rg[64 * 17];

    const int tid  = threadIdx.x;
    const int w    = tid >> 5;
    const int lane = tid & 31;
    const int g    = lane >> 2;       // groupID
    const int tq   = lane & 3;        // threadID_in_group
    const int mt   = w >> 1;
    const int nt   = w & 1;
    const int cta  = blockIdx.x;
    const int ug   = cta & 31;        // units [ug*16, +16)
    const int bg   = cta >> 5;        // batches [bg*16, +16)

    // ---- load A fragments (weights) into registers, once ----
    // a[ks][j]: halves (row, k),(row, k+1); row = mt*16 + g + (j&1)*8,
    // k = ks*16 + tq*2 + (j>>1)*8. Wh col = gate*512 + ug*16 + unit,
    // gate = row>>4, unit = row&15.
    unsigned ar[32][4];
#pragma unroll
    for (int ks = 0; ks < 32; ks++) {
#pragma unroll
        for (int j = 0; j < 4; j++) {
            int row  = mt * 16 + g + ((j & 1) << 3);
            int k    = ks * 16 + tq * 2 + ((j >> 1) << 3);
            int wcol = (row >> 4) * HID + (ug << 4) + (row & 15);
            float v0 = g_WhT[(size_t)wcol * HID + k];
            float v1 = g_WhT[(size_t)wcol * HID + k + 1];
            __half2 hv = __floats2half2_rn(v0, v1);
            ar[ks][j] = *(unsigned*)&hv;
        }
    }

    // B frag pointers: row n = nt*8 + g, k base = tq*2
    const __half* bhr = b_hi + (nt * 8 + g) * BST + tq * 2;
    const __half* blr = b_lo + (nt * 8 + g) * BST + tq * 2;

    const unsigned shi = (unsigned)__cvta_generic_to_shared(b_hi);
    const unsigned slo = (unsigned)__cvta_generic_to_shared(b_lo);

    // ---- activation mapping: (ab, au) ----
    const int ab = tid >> 4;
    const int au = tid & 15;
    const int gb = bg * 16 + ab;
    const int gj = (ug << 4) + au;

    unsigned int* barp = &g_barc[bg * 32];

    const size_t xof = (size_t)gb * G4 + gj;
    float c0 = g_xp[xof];
    float c1 = g_xp[xof + 512];
    float c2 = g_xp[xof + 1024];
    float c3 = g_xp[xof + 1536];

    float cval = 0.f;

    for (int t = 0; t < S_LEN; t++) {
        if (t > 0) {
            // ---- stage h(t-1) hi/lo fp16: 16 rows x 512 halves each ----
            const int pp = (t - 1) & 1;
            const __half* s_hi = g_hh[pp] + (size_t)(bg * 16) * HID;
            const __half* s_lo = g_hl[pp] + (size_t)(bg * 16) * HID;
#pragma unroll
            for (int i = 0; i < 8; i++) {          // 2048 16B-chunks / 256 thr
                int idx  = tid + (i << 8);
                int buf  = idx >> 10;              // 0: hi, 1: lo
                int rem  = idx & 1023;
                int lrow = rem >> 6;
                int ch   = rem & 63;
                const __half* src = (buf ? s_lo : s_hi) + lrow * HID + (ch << 3);
                unsigned dst = (buf ? slo : shi)
                               + (unsigned)(lrow * BST + (ch << 3)) * 2u;
                cpasync16(dst, (const void*)src);
            }
            asm volatile("cp.async.commit_group;");
            asm volatile("cp.async.wait_group 0;" ::: "memory");
            __syncthreads();
        }

        // prefetch xp(t+1)
        float n0 = 0.f, n1 = 0.f, n2 = 0.f, n3 = 0.f;
        if (t + 1 < S_LEN) {
            size_t nb = (size_t)(t + 1) * BG + xof;
            n0 = g_xp[nb]; n1 = g_xp[nb + 512];
            n2 = g_xp[nb + 1024]; n3 = g_xp[nb + 1536];
        }

        if (t > 0) {
            float d0 = 0.f, d1 = 0.f, d2 = 0.f, d3 = 0.f;
#pragma unroll
            for (int ks = 0; ks < 32; ks++) {
                unsigned b0h = *(const unsigned*)(bhr + ks * 16);
                unsigned b1h = *(const unsigned*)(bhr + ks * 16 + 8);
                unsigned b0l = *(const unsigned*)(blr + ks * 16);
                unsigned b1l = *(const unsigned*)(blr + ks * 16 + 8);
                hmma16816(d0, d1, d2, d3,
                          ar[ks][0], ar[ks][1], ar[ks][2], ar[ks][3], b0h, b1h);
                hmma16816(d0, d1, d2, d3,
                          ar[ks][0], ar[ks][1], ar[ks][2], ar[ks][3], b0l, b1l);
            }
            // D frag -> rg: c0(row g, col tq*2) c1(+1) c2(row g+8) c3(row g+8,+1)
            int row = mt * 16 + g;
            int col = nt * 8 + tq * 2;
            rg[row * 17 + col]           = d0;
            rg[row * 17 + col + 1]       = d1;
            rg[(row + 8) * 17 + col]     = d2;
            rg[(row + 8) * 17 + col + 1] = d3;
            __syncthreads();
        }

        // ---- activation: thread (ab, au) ----
        float gf = c0, gi = c1, go = c2, gg = c3;
        if (t > 0) {
            gf += rg[(au +  0) * 17 + ab];
            gi += rg[(au + 16) * 17 + ab];
            go += rg[(au + 32) * 17 + ab];
            gg += rg[(au + 48) * 17 + ab];
        }
        c0 = n0; c1 = n1; c2 = n2; c3 = n3;

        float fg = fast_sigmoid(gf);
        float ig = fast_sigmoid(gi);
        float og = fast_sigmoid(go);
        float gt = fast_tanh(gg);
        cval = fg * cval + ig * gt;
        float hval = og * fast_tanh(cval);

        out[(size_t)t * BH + (size_t)gb * HID + gj] = hval;
        {
            const int p = t & 1;
            __half hi = __float2half_rn(hval);
            __half lo = __float2half_rn(hval - __half2float(hi));
            g_hh[p][(size_t)gb * HID + gj] = hi;
            g_hl[p][(size_t)gb * HID + gj] = lo;
        }

        if (t < S_LEN - 1) {
            // ---- per-bg barrier: 32 arrivals ----
            __syncthreads();
            if (tid == 0) {
                asm volatile("red.release.gpu.global.add.u32 [%0], 1;"
                             :: "l"(barp) : "memory");
                unsigned target = (unsigned)(t + 1) * 32u;
                unsigned v;
                while (true) {
                    asm volatile("ld.acquire.gpu.global.u32 %0, [%1];"
                                 : "=r"(v) : "l"(barp) : "memory");
                    if (v >= target) break;
                    __nanosleep(20);
                }
            }
            __syncthreads();
        } else {
            out[(size_t)S_LEN * BH + (size_t)gb * HID + gj] = hval;        // h_f
            out[(size_t)S_LEN * BH + BH + (size_t)gb * HID + gj] = cval;   // c_f
        }
    }
}

// -------------------- launch ------------------------------------------------
extern "C" void kernel_launch(void* const* d_in, const int* in_sizes, int n_in,
                              void* d_out, int out_size)
{
    (void)in_sizes; (void)n_in; (void)out_size;
    const float* x   = (const float*)d_in[0];
    const float* Wxf = (const float*)d_in[1];
    const float* bxf = (const float*)d_in[2];
    const float* Whf = (const float*)d_in[3];
    const float* bhf = (const float*)d_in[4];
    const float* Wxi = (const float*)d_in[5];
    const float* bxi = (const float*)d_in[6];
    const float* Whi = (const float*)d_in[7];
    const float* bhi = (const float*)d_in[8];
    const float* Wxo = (const float*)d_in[9];
    const float* bxo = (const float*)d_in[10];
    const float* Who = (const float*)d_in[11];
    const float* bho = (const float*)d_in[12];
    const float* Wxg = (const float*)d_in[13];
    const float* bxg = (const float*)d_in[14];
    const float* Whg = (const float*)d_in[15];
    const float* bhg = (const float*)d_in[16];
    float* out = (float*)d_out;

    prep_kernel<<<(G4 * HID + 255) / 256, 256>>>(
        Wxf, Wxi, Wxo, Wxg, Whf, Whi, Who, Whg,
        bxf, bhf, bxi, bhi, bxo, bho, bxg, bhg);

    dim3 gproj(G4 / 64, (S_LEN * BATCH) / 128);
    xproj_kernel<<<gproj, 256>>>(x);

    lstm_rec_kernel<<<NCTA, 256>>>(out);
}

// round 10
// speedup vs baseline: 3.2047x; 1.1536x over previous
#include <cuda_runtime.h>
#include <cuda_bf16.h>
#include <cuda_fp16.h>
#include <math.h>

// ---------------------------------------------------------------------------
// LSTM: S=512, B=64, I=256, H=512
// out = [h_seq (S,B,H) | h_final (B,H) | c_final (B,H)]  (fp32)
// xproj + recurrence both on mma.sync m16n8k16 (hi/lo fp16 splits ~ fp32).
// ---------------------------------------------------------------------------

#define S_LEN 512
#define BATCH 64
#define IN_DIM 256
#define HID 512
#define G4 2048              // 4*H
#define BH (BATCH*HID)       // 32768
#define BG (BATCH*G4)        // 131072
#define NCTA 128
#define BST 520              // rec B smem row stride (halves)

// xproj tiling
#define XM 64
#define XN 256
#define XBK 32
#define XST 40               // xproj smem row stride (halves): 20 words/row
#define XA_BUF (XM*XST)      // 2560 halves per A buffer
#define XB_BUF (XN*XST)      // 10240 halves per B buffer
#define XP_SMEM ((4*XA_BUF + 2*XB_BUF) * 2)   // 61440 bytes

// -------------------- device scratch (static: no allocs allowed) ------------
__device__ float  g_xp[(size_t)S_LEN * BATCH * G4];  // x@Wx + bx + bh
__device__ __half g_WxT[(size_t)G4 * IN_DIM];        // WxT[n][k] fp16
__device__ float  g_WhT[(size_t)G4 * HID];           // WhT[col][k]
__device__ float  g_bias[G4];                        // bx + bh
__device__ __half g_hh[2][BH];                       // h hi fp16, ping-pong
__device__ __half g_hl[2][BH];                       // h lo fp16, ping-pong
__device__ unsigned int g_barc[4 * 32];              // per-bg counters

// fast activations
__device__ __forceinline__ float fast_exp(float x) {
    float e;
    asm("ex2.approx.f32 %0, %1;" : "=f"(e) : "f"(x * 1.4426950408889634f));
    return e;
}
__device__ __forceinline__ float fast_rcp(float x) {
    float r;
    asm("rcp.approx.f32 %0, %1;" : "=f"(r) : "f"(x));
    return r;
}
__device__ __forceinline__ float fast_sigmoid(float x) {
    return fast_rcp(1.f + fast_exp(-x));
}
__device__ __forceinline__ float fast_tanh(float x) {
    return 2.f * fast_rcp(1.f + fast_exp(-2.f * x)) - 1.f;
}

__device__ __forceinline__ void cpasync16(unsigned dst, const void* src) {
    asm volatile("cp.async.cg.shared.global [%0], [%1], 16;"
                 :: "r"(dst), "l"(src));
}

// mma.sync m16n8k16 row.col f32.f16.f16.f32 (accumulate in place)
__device__ __forceinline__ void hmma16816(float& d0, float& d1, float& d2, float& d3,
                                          unsigned a0, unsigned a1, unsigned a2, unsigned a3,
                                          unsigned b0, unsigned b1) {
    asm volatile(
        "mma.sync.aligned.m16n8k16.row.col.f32.f16.f16.f32 "
        "{%0,%1,%2,%3}, {%4,%5,%6,%7}, {%8,%9}, {%0,%1,%2,%3};"
        : "+f"(d0), "+f"(d1), "+f"(d2), "+f"(d3)
        : "r"(a0), "r"(a1), "r"(a2), "r"(a3), "r"(b0), "r"(b1));
}

// -------------------- merged prep kernel --------------------------------------
__global__ void prep_kernel(
    const float* __restrict__ Wxf, const float* __restrict__ Wxi,
    const float* __restrict__ Wxo, const float* __restrict__ Wxg,
    const float* __restrict__ Whf, const float* __restrict__ Whi,
    const float* __restrict__ Who, const float* __restrict__ Whg,
    const float* __restrict__ bxf, const float* __restrict__ bhf,
    const float* __restrict__ bxi, const float* __restrict__ bhi,
    const float* __restrict__ bxo, const float* __restrict__ bho,
    const float* __restrict__ bxg, const float* __restrict__ bhg)
{
    int idx = blockIdx.x * blockDim.x + threadIdx.x;

    if (idx < 4 * 32) g_barc[idx] = 0u;

    if (idx < G4) {
        int g = idx >> 9, jj = idx & 511;
        const float* bx = (g == 0) ? bxf : (g == 1) ? bxi : (g == 2) ? bxo : bxg;
        const float* bh = (g == 0) ? bhf : (g == 1) ? bhi : (g == 2) ? bho : bhg;
        g_bias[idx] = bx[jj] + bh[jj];
    }

    if (idx < G4 * IN_DIM) {         // g_WxT[n][k] = Wx_gate[k][unit] fp16
        int n = idx >> 8;
        int k = idx & 255;
        int g = n >> 9, unit = n & 511;
        const float* W = (g == 0) ? Wxf : (g == 1) ? Wxi : (g == 2) ? Wxo : Wxg;
        g_WxT[idx] = __float2half_rn(W[k * HID + unit]);
    }

    if (idx < G4 * HID) {
        int col = idx >> 9;
        int k   = idx & 511;
        int g   = col >> 9;
        int jj  = col & 511;
        const float* W = (g == 0) ? Whf : (g == 1) ? Whi : (g == 2) ? Who : Whg;
        g_WhT[idx] = W[k * HID + jj];   // WhT[col][k] = Wh[k][col]
    }
}

// -------------------- xproj via mma.sync ---------------------------------------
// xp[m][n] = sum_k x[m][k]*Wx[k][n] + bias[n].
// CTA tile 64x256, BK=32, 8 warps (2 m-tiles x 4 n-tiles of 32x64).
// A = x as hi+lo fp16 (2 passes ~ fp32); B = WxT fp16 (single).
// Double-buffered smem; B via cp.async, A via LDG->convert->STS.
__global__ __launch_bounds__(256) void xproj_hmma(const float* __restrict__ x)
{
    extern __shared__ __half xs[];
    __half* a_hi = xs;                       // 2 x XA_BUF
    __half* a_lo = xs + 2 * XA_BUF;          // 2 x XA_BUF
    __half* bsm  = xs + 4 * XA_BUF;          // 2 x XB_BUF

    const int tid  = threadIdx.x;
    const int w    = tid >> 5;
    const int lane = tid & 31;
    const int g    = lane >> 2;
    const int tq   = lane & 3;
    const int mw   = w >> 2;                 // 0..1
    const int nw   = w & 3;                  // 0..3
    const int bm   = blockIdx.y * XM;
    const int bn   = blockIdx.x * XN;

    const int arow = tid >> 2;               // 0..63
    const int aq   = tid & 3;                // k-chunk of 8 floats
    const float* axp = x + (size_t)(bm + arow) * IN_DIM + aq * 8;

    const unsigned sb   = (unsigned)__cvta_generic_to_shared(xs);
    const unsigned bsmb = sb + (unsigned)(4 * XA_BUF) * 2u;

    float acc[2][8][4];
#pragma unroll
    for (int f = 0; f < 2; f++)
#pragma unroll
        for (int nf = 0; nf < 8; nf++)
#pragma unroll
            for (int q = 0; q < 4; q++) acc[f][nf][q] = 0.f;

    // ---- helpers as macros over locals ----
#define CPB(p, ktg)                                                          \
    do {                                                                     \
        _Pragma("unroll")                                                    \
        for (int i = 0; i < 4; i++) {                                        \
            int idx = tid + (i << 8);                                        \
            int n   = idx >> 2;                                              \
            int ko  = (idx & 3) << 3;                                        \
            unsigned dst = bsmb + (unsigned)((p) * XB_BUF + n * XST + ko) * 2u; \
            cpasync16(dst, (const void*)(g_WxT + (size_t)(bn + n) * IN_DIM + (ktg) + ko)); \
        }                                                                    \
    } while (0)

#define STAGEA(p, v0, v1)                                                    \
    do {                                                                     \
        float ff[8] = {v0.x, v0.y, v0.z, v0.w, v1.x, v1.y, v1.z, v1.w};      \
        __align__(16) __half hh[8];                                          \
        __align__(16) __half hl[8];                                          \
        _Pragma("unroll")                                                    \
        for (int i = 0; i < 8; i++) {                                        \
            hh[i] = __float2half_rn(ff[i]);                                  \
            hl[i] = __float2half_rn(ff[i] - __half2float(hh[i]));            \
        }                                                                    \
        *(uint4*)(a_hi + (p) * XA_BUF + arow * XST + aq * 8) = *(uint4*)hh;  \
        *(uint4*)(a_lo + (p) * XA_BUF + arow * XST + aq * 8) = *(uint4*)hl;  \
    } while (0)

    // ---- prologue: tile 0 ----
    {
        CPB(0, 0);
        asm volatile("cp.async.commit_group;");
        float4 v0 = *(const float4*)(axp);
        float4 v1 = *(const float4*)(axp + 4);
        STAGEA(0, v0, v1);
        asm volatile("cp.async.wait_group 0;" ::: "memory");
    }
    __syncthreads();

#pragma unroll
    for (int kt = 0; kt < IN_DIM / XBK; kt++) {
        const int p = kt & 1;
        const bool has_next = (kt + 1) < (IN_DIM / XBK);

        float4 nv0, nv1;
        if (has_next) {
            CPB(p ^ 1, (kt + 1) * XBK);
            asm volatile("cp.async.commit_group;");
            nv0 = *(const float4*)(axp + (kt + 1) * XBK);
            nv1 = *(const float4*)(axp + (kt + 1) * XBK + 4);
        }

        const __half* ah_p = a_hi + p * XA_BUF;
        const __half* al_p = a_lo + p * XA_BUF;
        const __half* b_p  = bsm + p * XB_BUF;

#pragma unroll
        for (int ks = 0; ks < 2; ks++) {
            unsigned AH[2][4], AL[2][4], BB[8][2];
#pragma unroll
            for (int f = 0; f < 2; f++)
#pragma unroll
                for (int j = 0; j < 4; j++) {
                    int row = mw * 32 + f * 16 + g + ((j & 1) << 3);
                    int k   = ks * 16 + tq * 2 + ((j >> 1) << 3);
                    AH[f][j] = *(const unsigned*)(ah_p + row * XST + k);
                    AL[f][j] = *(const unsigned*)(al_p + row * XST + k);
                }
#pragma unroll
            for (int nf = 0; nf < 8; nf++) {
                int n = nw * 64 + nf * 8 + g;
                BB[nf][0] = *(const unsigned*)(b_p + n * XST + ks * 16 + tq * 2);
                BB[nf][1] = *(const unsigned*)(b_p + n * XST + ks * 16 + tq * 2 + 8);
            }
#pragma unroll
            for (int f = 0; f < 2; f++)
#pragma unroll
                for (int nf = 0; nf < 8; nf++) {
                    hmma16816(acc[f][nf][0], acc[f][nf][1], acc[f][nf][2], acc[f][nf][3],
                              AH[f][0], AH[f][1], AH[f][2], AH[f][3],
                              BB[nf][0], BB[nf][1]);
                    hmma16816(acc[f][nf][0], acc[f][nf][1], acc[f][nf][2], acc[f][nf][3],
                              AL[f][0], AL[f][1], AL[f][2], AL[f][3],
                              BB[nf][0], BB[nf][1]);
                }
        }

        if (has_next) {
            STAGEA(p ^ 1, nv0, nv1);
            asm volatile("cp.async.wait_group 0;" ::: "memory");
            __syncthreads();
        }
    }

    // ---- epilogue: bias add + store ----
#pragma unroll
    for (int nf = 0; nf < 8; nf++) {
        int col = bn + nw * 64 + nf * 8 + tq * 2;
        float b0 = g_bias[col];
        float b1 = g_bias[col + 1];
#pragma unroll
        for (int f = 0; f < 2; f++) {
            int r0 = bm + mw * 32 + f * 16 + g;
            float2 o0 = make_float2(acc[f][nf][0] + b0, acc[f][nf][1] + b1);
            float2 o1 = make_float2(acc[f][nf][2] + b0, acc[f][nf][3] + b1);
            *(float2*)&g_xp[(size_t)r0 * G4 + col]       = o0;
            *(float2*)&g_xp[(size_t)(r0 + 8) * G4 + col] = o1;
        }
    }
#undef CPB
#undef STAGEA
}

// -------------------- recurrence: mma.sync persistent (unchanged R9) ----------
__global__ __launch_bounds__(256, 1) void lstm_rec_kernel(float* __restrict__ out)
{
    __shared__ __align__(16) __half b_hi[16 * BST];
    __shared__ __align__(16) __half b_lo[16 * BST];
    __shared__ float rg[64 * 17];

    const int tid  = threadIdx.x;
    const int w    = tid >> 5;
    const int lane = tid & 31;
    const int g    = lane >> 2;
    const int tq   = lane & 3;
    const int mt   = w >> 1;
    const int nt   = w & 1;
    const int cta  = blockIdx.x;
    const int ug   = cta & 31;
    const int bg   = cta >> 5;

    unsigned ar[32][4];
#pragma unroll
    for (int ks = 0; ks < 32; ks++) {
#pragma unroll
        for (int j = 0; j < 4; j++) {
            int row  = mt * 16 + g + ((j & 1) << 3);
            int k    = ks * 16 + tq * 2 + ((j >> 1) << 3);
            int wcol = (row >> 4) * HID + (ug << 4) + (row & 15);
            float v0 = g_WhT[(size_t)wcol * HID + k];
            float v1 = g_WhT[(size_t)wcol * HID + k + 1];
            __half2 hv = __floats2half2_rn(v0, v1);
            ar[ks][j] = *(unsigned*)&hv;
        }
    }

    const __half* bhr = b_hi + (nt * 8 + g) * BST + tq * 2;
    const __half* blr = b_lo + (nt * 8 + g) * BST + tq * 2;

    const unsigned shi = (unsigned)__cvta_generic_to_shared(b_hi);
    const unsigned slo = (unsigned)__cvta_generic_to_shared(b_lo);

    const int ab = tid >> 4;
    const int au = tid & 15;
    const int gb = bg * 16 + ab;
    const int gj = (ug << 4) + au;

    unsigned int* barp = &g_barc[bg * 32];

    const size_t xof = (size_t)gb * G4 + gj;
    float c0 = g_xp[xof];
    float c1 = g_xp[xof + 512];
    float c2 = g_xp[xof + 1024];
    float c3 = g_xp[xof + 1536];

    float cval = 0.f;

    for (int t = 0; t < S_LEN; t++) {
        if (t > 0) {
            const int pp = (t - 1) & 1;
            const __half* s_hi = g_hh[pp] + (size_t)(bg * 16) * HID;
            const __half* s_lo = g_hl[pp] + (size_t)(bg * 16) * HID;
#pragma unroll
            for (int i = 0; i < 8; i++) {
                int idx  = tid + (i << 8);
                int buf  = idx >> 10;
                int rem  = idx & 1023;
                int lrow = rem >> 6;
                int ch   = rem & 63;
                const __half* src = (buf ? s_lo : s_hi) + lrow * HID + (ch << 3);
                unsigned dst = (buf ? slo : shi)
                               + (unsigned)(lrow * BST + (ch << 3)) * 2u;
                cpasync16(dst, (const void*)src);
            }
            asm volatile("cp.async.commit_group;");
            asm volatile("cp.async.wait_group 0;" ::: "memory");
            __syncthreads();
        }

        float n0 = 0.f, n1 = 0.f, n2 = 0.f, n3 = 0.f;
        if (t + 1 < S_LEN) {
            size_t nb = (size_t)(t + 1) * BG + xof;
            n0 = g_xp[nb]; n1 = g_xp[nb + 512];
            n2 = g_xp[nb + 1024]; n3 = g_xp[nb + 1536];
        }

        if (t > 0) {
            float d0 = 0.f, d1 = 0.f, d2 = 0.f, d3 = 0.f;
#pragma unroll
            for (int ks = 0; ks < 32; ks++) {
                unsigned b0h = *(const unsigned*)(bhr + ks * 16);
                unsigned b1h = *(const unsigned*)(bhr + ks * 16 + 8);
                unsigned b0l = *(const unsigned*)(blr + ks * 16);
                unsigned b1l = *(const unsigned*)(blr + ks * 16 + 8);
                hmma16816(d0, d1, d2, d3,
                          ar[ks][0], ar[ks][1], ar[ks][2], ar[ks][3], b0h, b1h);
                hmma16816(d0, d1, d2, d3,
                          ar[ks][0], ar[ks][1], ar[ks][2], ar[ks][3], b0l, b1l);
            }
            int row = mt * 16 + g;
            int col = nt * 8 + tq * 2;
            rg[row * 17 + col]           = d0;
            rg[row * 17 + col + 1]       = d1;
            rg[(row + 8) * 17 + col]     = d2;
            rg[(row + 8) * 17 + col + 1] = d3;
            __syncthreads();
        }

        float gf = c0, gi = c1, go = c2, gg = c3;
        if (t > 0) {
            gf += rg[(au +  0) * 17 + ab];
            gi += rg[(au + 16) * 17 + ab];
            go += rg[(au + 32) * 17 + ab];
            gg += rg[(au + 48) * 17 + ab];
        }
        c0 = n0; c1 = n1; c2 = n2; c3 = n3;

        float fg = fast_sigmoid(gf);
        float ig = fast_sigmoid(gi);
        float og = fast_sigmoid(go);
        float gt = fast_tanh(gg);
        cval = fg * cval + ig * gt;
        float hval = og * fast_tanh(cval);

        out[(size_t)t * BH + (size_t)gb * HID + gj] = hval;
        {
            const int p = t & 1;
            __half hi = __float2half_rn(hval);
            __half lo = __float2half_rn(hval - __half2float(hi));
            g_hh[p][(size_t)gb * HID + gj] = hi;
            g_hl[p][(size_t)gb * HID + gj] = lo;
        }

        if (t < S_LEN - 1) {
            __syncthreads();
            if (tid == 0) {
                asm volatile("red.release.gpu.global.add.u32 [%0], 1;"
                             :: "l"(barp) : "memory");
                unsigned target = (unsigned)(t + 1) * 32u;
                unsigned v;
                while (true) {
                    asm volatile("ld.acquire.gpu.global.u32 %0, [%1];"
                                 : "=r"(v) : "l"(barp) : "memory");
                    if (v >= target) break;
                    __nanosleep(20);
                }
            }
            __syncthreads();
        } else {
            out[(size_t)S_LEN * BH + (size_t)gb * HID + gj] = hval;        // h_f
            out[(size_t)S_LEN * BH + BH + (size_t)gb * HID + gj] = cval;   // c_f
        }
    }
}

// -------------------- launch ------------------------------------------------
extern "C" void kernel_launch(void* const* d_in, const int* in_sizes, int n_in,
                              void* d_out, int out_size)
{
    (void)in_sizes; (void)n_in; (void)out_size;
    const float* x   = (const float*)d_in[0];
    const float* Wxf = (const float*)d_in[1];
    const float* bxf = (const float*)d_in[2];
    const float* Whf = (const float*)d_in[3];
    const float* bhf = (const float*)d_in[4];
    const float* Wxi = (const float*)d_in[5];
    const float* bxi = (const float*)d_in[6];
    const float* Whi = (const float*)d_in[7];
    const float* bhi = (const float*)d_in[8];
    const float* Wxo = (const float*)d_in[9];
    const float* bxo = (const float*)d_in[10];
    const float* Who = (const float*)d_in[11];
    const float* bho = (const float*)d_in[12];
    const float* Wxg = (const float*)d_in[13];
    const float* bxg = (const float*)d_in[14];
    const float* Whg = (const float*)d_in[15];
    const float* bhg = (const float*)d_in[16];
    float* out = (float*)d_out;

    prep_kernel<<<(G4 * HID + 255) / 256, 256>>>(
        Wxf, Wxi, Wxo, Wxg, Whf, Whi, Who, Whg,
        bxf, bhf, bxi, bhi, bxo, bho, bxg, bhg);

    static bool attr_set = false;
    if (!attr_set) {
        cudaFuncSetAttribute(xproj_hmma,
                             cudaFuncAttributeMaxDynamicSharedMemorySize, XP_SMEM);
        attr_set = true;
    }
    dim3 gproj(G4 / XN, (S_LEN * BATCH) / XM);
    xproj_hmma<<<gproj, 256, XP_SMEM>>>(x);

    lstm_rec_kernel<<<NCTA, 256>>>(out);
}